// round 3
// baseline (speedup 1.0000x reference)
#include <cuda_runtime.h>
#include <math.h>

#define NNODES 50000
#define NEDGES 800000
#define NAUG   (NEDGES + NNODES)   // edges + self loops

// ---------------- scratch (device globals; no allocation allowed) ----------------
__device__ float g_x   [(size_t)NNODES * 512];   // concat [x_proj | edge_proj]
__device__ float g_xh  [(size_t)NNODES * 256];   // per-layer head features
__device__ float g_x2  [(size_t)NNODES * 256];   // layer output
__device__ float g_ne  [(size_t)NNODES * 16];    // edge_attr sums
__device__ float g_cnt [NNODES];                 // edge counts
__device__ float g_asrc[NNODES * 4];
__device__ float g_adst[NNODES * 4];
__device__ int   g_deg   [NNODES];
__device__ int   g_rowptr[NNODES + 1];
__device__ int   g_cursor[NNODES];
__device__ int   g_einc  [NAUG];                 // src node per incoming edge (CSR)

// ---------------- helpers ----------------
__device__ __forceinline__ float lrelu(float x) { return x > 0.f ? x : 0.2f * x; }

__device__ __forceinline__ unsigned int cvt_tf32(float x) {
    unsigned int u;
    asm("cvt.rna.tf32.f32 %0, %1;" : "=r"(u) : "f"(x));
    return u;
}
// split x into hi (tf32) + lo (tf32) s.t. hi+lo ~= x
__device__ __forceinline__ void split_tf32(float x, float& h, float& l) {
    unsigned int uh = cvt_tf32(x);
    h = __uint_as_float(uh);
    l = __uint_as_float(cvt_tf32(x - h));
}
__device__ __forceinline__ void mma_tf32(float* d, unsigned int a0, unsigned int a1,
                                         unsigned int a2, unsigned int a3,
                                         unsigned int b0, unsigned int b1) {
    asm("mma.sync.aligned.m16n8k8.row.col.f32.tf32.tf32.f32 "
        "{%0,%1,%2,%3},{%4,%5,%6,%7},{%8,%9},{%0,%1,%2,%3};"
        : "+f"(d[0]), "+f"(d[1]), "+f"(d[2]), "+f"(d[3])
        : "r"(a0), "r"(a1), "r"(a2), "r"(a3), "r"(b0), "r"(b1));
}

// ---------------- generic zero ----------------
__global__ void zero_kernel(float* p, size_t n) {
    size_t i = (size_t)blockIdx.x * blockDim.x + threadIdx.x;
    if (i < n) p[i] = 0.f;
}

// ---------------- tf32x3 tensor-core GEMM: C[M,N]=A[M,K]@B[K,N](+bias) ----------------
// BM=128, BN=128, BK=16. 8 warps: warp_m=wid&3 (32 rows), warp_n=wid>>1... (see below)
// warp tile 32x64 = 2 mfrag x 8 nfrag of m16n8k8.
__global__ __launch_bounds__(256, 2) void mma_gemm(
    const float* __restrict__ A, const float* __restrict__ B,
    const float* __restrict__ bias, float* __restrict__ C,
    int M, int N, int K, int lda, int ldc, int cofs)
{
    // smem planes: [kstep(2)][row(128)][pairidx(8)] floats, fragment-native layout:
    // element (row, k): idx = (k&3)*2 + ((k&7)>>2), kstep = k>>3
    __shared__ float Ah[2][128][8], Al[2][128][8];
    __shared__ float Bh[2][128][8], Bl[2][128][8];

    int tid  = threadIdx.x;
    int wid  = tid >> 5;
    int lane = tid & 31;
    int warp_m = (wid & 3) * 32;       // 4 warps in m
    int warp_n = (wid >> 2) * 64;      // 2 warps in n
    int brow = blockIdx.y, bcol = blockIdx.x;
    int lane4 = lane >> 2;             // groupID 0..7
    int lmod  = lane & 3;

    float d[2][8][4];
    #pragma unroll
    for (int i = 0; i < 2; i++)
        #pragma unroll
        for (int j = 0; j < 8; j++)
            #pragma unroll
            for (int k = 0; k < 4; k++) d[i][j][k] = 0.f;

    for (int k0 = 0; k0 < K; k0 += 16) {
        // ---- load A tile 128x16 (split to tf32 hi/lo) ----
        #pragma unroll
        for (int i = 0; i < 2; i++) {
            int f4 = tid * 2 + i;              // 0..511
            int arow = f4 >> 2;
            int acol = (f4 & 3) * 4;
            int grow = brow * 128 + arow;
            float4 av = make_float4(0.f, 0.f, 0.f, 0.f);
            if (grow < M) av = *(const float4*)(A + (size_t)grow * lda + k0 + acol);
            float e[4] = {av.x, av.y, av.z, av.w};
            #pragma unroll
            for (int q = 0; q < 4; q++) {
                int k = acol + q;
                int ks = k >> 3, kk = k & 7;
                int idx = (kk & 3) * 2 + (kk >> 2);
                float h, l; split_tf32(e[q], h, l);
                Ah[ks][arow][idx] = h;
                Al[ks][arow][idx] = l;
            }
        }
        // ---- load B tile 16x128 (split) ----
        #pragma unroll
        for (int i = 0; i < 2; i++) {
            int f4 = tid * 2 + i;
            int krow = f4 >> 5;                // 0..15
            int ncol = (f4 & 31) * 4;
            float4 bv = *(const float4*)(B + (size_t)(k0 + krow) * N + bcol * 128 + ncol);
            float e[4] = {bv.x, bv.y, bv.z, bv.w};
            int ks = krow >> 3, kk = krow & 7;
            int idx = (kk & 3) * 2 + (kk >> 2);
            #pragma unroll
            for (int q = 0; q < 4; q++) {
                float h, l; split_tf32(e[q], h, l);
                Bh[ks][ncol + q][idx] = h;
                Bl[ks][ncol + q][idx] = l;
            }
        }
        __syncthreads();

        #pragma unroll
        for (int ks = 0; ks < 2; ks++) {
            // A fragments: (a0,a2) at row, (a1,a3) at row+8; pair = (k, k+4)
            unsigned int ah[2][4], al[2][4];
            #pragma unroll
            for (int mf = 0; mf < 2; mf++) {
                int r = warp_m + mf * 16 + lane4;
                float2 h0 = *(const float2*)&Ah[ks][r][lmod * 2];
                float2 h1 = *(const float2*)&Ah[ks][r + 8][lmod * 2];
                float2 l0 = *(const float2*)&Al[ks][r][lmod * 2];
                float2 l1 = *(const float2*)&Al[ks][r + 8][lmod * 2];
                ah[mf][0] = __float_as_uint(h0.x); ah[mf][1] = __float_as_uint(h1.x);
                ah[mf][2] = __float_as_uint(h0.y); ah[mf][3] = __float_as_uint(h1.y);
                al[mf][0] = __float_as_uint(l0.x); al[mf][1] = __float_as_uint(l1.x);
                al[mf][2] = __float_as_uint(l0.y); al[mf][3] = __float_as_uint(l1.y);
            }
            #pragma unroll
            for (int nf = 0; nf < 8; nf++) {
                int n = warp_n + nf * 8 + lane4;
                float2 bhv = *(const float2*)&Bh[ks][n][lmod * 2];
                float2 blv = *(const float2*)&Bl[ks][n][lmod * 2];
                unsigned int b0h = __float_as_uint(bhv.x), b1h = __float_as_uint(bhv.y);
                unsigned int b0l = __float_as_uint(blv.x), b1l = __float_as_uint(blv.y);
                #pragma unroll
                for (int mf = 0; mf < 2; mf++) {
                    mma_tf32(d[mf][nf], ah[mf][0], ah[mf][1], ah[mf][2], ah[mf][3], b0h, b1h);
                    mma_tf32(d[mf][nf], al[mf][0], al[mf][1], al[mf][2], al[mf][3], b0h, b1h);
                    mma_tf32(d[mf][nf], ah[mf][0], ah[mf][1], ah[mf][2], ah[mf][3], b0l, b1l);
                }
            }
        }
        __syncthreads();
    }

    // ---- epilogue ----
    #pragma unroll
    for (int mf = 0; mf < 2; mf++) {
        #pragma unroll
        for (int half = 0; half < 2; half++) {
            int gr = brow * 128 + warp_m + mf * 16 + lane4 + half * 8;
            if (gr >= M) continue;
            #pragma unroll
            for (int nf = 0; nf < 8; nf++) {
                int gc = bcol * 128 + warp_n + nf * 8 + lmod * 2;
                float2 v;
                v.x = d[mf][nf][half * 2 + 0] + (bias ? bias[gc + 0] : 0.f);
                v.y = d[mf][nf][half * 2 + 1] + (bias ? bias[gc + 1] : 0.f);
                *(float2*)(C + (size_t)gr * ldc + cofs + gc) = v;
            }
        }
    }
}

// ---------------- scatter mean of edge_attr over dst ----------------
__global__ void edge_mean_kernel(const float* __restrict__ ea, const int* __restrict__ ei) {
    int i = blockIdx.x * blockDim.x + threadIdx.x;
    if (i >= NEDGES * 16) return;
    int e = i >> 4, k = i & 15;
    int d = ei[NEDGES + e];
    atomicAdd(&g_ne[(size_t)d * 16 + k], ea[i]);
    if (k == 0) atomicAdd(&g_cnt[d], 1.f);
}

// ---------------- nef = (sum/cnt) @ Wep + bep -> g_x[:,256:512] ----------------
__global__ __launch_bounds__(256) void nef_kernel(const float* __restrict__ Wep,
                                                  const float* __restrict__ bep) {
    __shared__ float s[16];
    int node = blockIdx.x;
    if (threadIdx.x < 16) {
        float c = g_cnt[node];
        c = c < 1.f ? 1.f : c;
        s[threadIdx.x] = g_ne[(size_t)node * 16 + threadIdx.x] / c;
    }
    __syncthreads();
    int c = threadIdx.x;
    float acc = bep[c];
    #pragma unroll
    for (int k = 0; k < 16; k++) acc += s[k] * Wep[k * 256 + c];
    g_x[(size_t)node * 512 + 256 + c] = acc;
}

// ---------------- CSR build ----------------
__global__ void hist_kernel(const int* __restrict__ ei) {
    int e = blockIdx.x * blockDim.x + threadIdx.x;
    if (e >= NAUG) return;
    int d = (e < NEDGES) ? ei[NEDGES + e] : e - NEDGES;
    atomicAdd(&g_deg[d], 1);
}

#define SCAN_T 1024
__global__ __launch_bounds__(SCAN_T) void scan_kernel() {
    __shared__ int part[SCAN_T];
    int t = threadIdx.x;
    const int CH = (NNODES + SCAN_T - 1) / SCAN_T;
    int base = t * CH;
    int sum = 0;
    for (int i = 0; i < CH; i++) {
        int idx = base + i;
        if (idx < NNODES) sum += g_deg[idx];
    }
    part[t] = sum;
    __syncthreads();
    for (int off = 1; off < SCAN_T; off <<= 1) {
        int v = (t >= off) ? part[t - off] : 0;
        __syncthreads();
        part[t] += v;
        __syncthreads();
    }
    int run = part[t] - sum;   // exclusive prefix
    for (int i = 0; i < CH; i++) {
        int idx = base + i;
        if (idx < NNODES) {
            g_rowptr[idx] = run;
            g_cursor[idx] = run;
            run += g_deg[idx];
        }
    }
    if (t == SCAN_T - 1) g_rowptr[NNODES] = NAUG;
}

__global__ void scatter_kernel(const int* __restrict__ ei) {
    int e = blockIdx.x * blockDim.x + threadIdx.x;
    if (e >= NAUG) return;
    int s, d;
    if (e < NEDGES) { s = ei[e]; d = ei[NEDGES + e]; }
    else            { s = d = e - NEDGES; }
    int pos = atomicAdd(&g_cursor[d], 1);
    g_einc[pos] = s;
}

// ---------------- per-node attention coefficients ----------------
__global__ void att_kernel(const float* __restrict__ as, const float* __restrict__ ad) {
    int w = (blockIdx.x * blockDim.x + threadIdx.x) >> 5;
    int lane = threadIdx.x & 31;
    if (w >= NNODES * 4) return;
    int node = w >> 2, h = w & 3;
    const float* xr = g_xh + (size_t)node * 256 + h * 64;
    float s1 = xr[lane] * as[h * 64 + lane] + xr[lane + 32] * as[h * 64 + lane + 32];
    float s2 = xr[lane] * ad[h * 64 + lane] + xr[lane + 32] * ad[h * 64 + lane + 32];
    #pragma unroll
    for (int o = 16; o; o >>= 1) {
        s1 += __shfl_down_sync(0xffffffffu, s1, o);
        s2 += __shfl_down_sync(0xffffffffu, s2, o);
    }
    if (lane == 0) {
        g_asrc[w] = s1;
        g_adst[w] = s2;
    }
}

// ---------------- fused GAT: online softmax + gather-aggregate + bias + ELU ----------------
__global__ __launch_bounds__(256) void gat_fused(const float* __restrict__ bias,
                                                 float* __restrict__ out) {
    __shared__ float sm[256];
    __shared__ float sd[256];
    int node = blockIdx.x;
    int tid = threadIdx.x;
    int beg = g_rowptr[node], end = g_rowptr[node + 1];
    int deg = end - beg;

    // Phase 1: online softmax stats. thread = (e-slot, head)
    int h = tid & 3;
    int es = tid >> 2;                 // 0..63
    float adst = g_adst[node * 4 + h];
    float m = -INFINITY, dsum = 0.f;
    for (int i = es; i < deg; i += 64) {
        int s = g_einc[beg + i];
        float l = lrelu(g_asrc[s * 4 + h] + adst);
        if (l > m) { dsum = dsum * __expf(m - l) + 1.f; m = l; }
        else       { dsum += __expf(l - m); }
    }
    sm[tid] = m; sd[tid] = dsum;
    __syncthreads();
    #pragma unroll
    for (int s = 32; s >= 1; s >>= 1) {
        if (es < s) {
            float m1 = sm[tid], d1 = sd[tid];
            float m2 = sm[tid + 4 * s], d2 = sd[tid + 4 * s];
            float M = fmaxf(m1, m2);
            float e1 = (m1 == -INFINITY) ? 0.f : __expf(m1 - M);
            float e2 = (m2 == -INFINITY) ? 0.f : __expf(m2 - M);
            sm[tid] = M;
            sd[tid] = d1 * e1 + d2 * e2;
        }
        __syncthreads();
    }

    // Phase 2: aggregate. thread = feature; head = tid>>6
    int h2 = tid >> 6;
    float M = sm[h2];
    float Dinv = 1.f / sd[h2];
    float adst2 = g_adst[node * 4 + h2];
    float acc = 0.f;
    for (int e = beg; e < end; e++) {
        int s = g_einc[e];
        float l = lrelu(g_asrc[s * 4 + h2] + adst2);
        float alpha = __expf(l - M) * Dinv;
        acc += alpha * g_xh[(size_t)s * 256 + tid];
    }
    float v = acc + bias[tid];
    out[(size_t)node * 256 + tid] = v > 0.f ? v : expm1f(v);
}

// ---------------- host launch ----------------
extern "C" void kernel_launch(void* const* d_in, const int* in_sizes, int n_in,
                              void* d_out, int out_size) {
    const float* node_feats = (const float*)d_in[0];
    const float* edge_attr  = (const float*)d_in[1];
    const float* Wnp = (const float*)d_in[2];
    const float* bnp = (const float*)d_in[3];
    const float* Wep = (const float*)d_in[4];
    const float* bep = (const float*)d_in[5];
    const float* Wg1 = (const float*)d_in[6];
    const float* as1 = (const float*)d_in[7];
    const float* ad1 = (const float*)d_in[8];
    const float* bg1 = (const float*)d_in[9];
    const float* Wg2 = (const float*)d_in[10];
    const float* as2 = (const float*)d_in[11];
    const float* ad2 = (const float*)d_in[12];
    const float* bg2 = (const float*)d_in[13];
    const float* Wo  = (const float*)d_in[14];
    const float* bo  = (const float*)d_in[15];
    const int*   ei  = (const int*)d_in[16];
    float* out = (float*)d_out;

    float *px, *pxh, *px2, *pne, *pcnt;
    int* pdeg;
    cudaGetSymbolAddress((void**)&px,   g_x);
    cudaGetSymbolAddress((void**)&pxh,  g_xh);
    cudaGetSymbolAddress((void**)&px2,  g_x2);
    cudaGetSymbolAddress((void**)&pne,  g_ne);
    cudaGetSymbolAddress((void**)&pcnt, g_cnt);
    cudaGetSymbolAddress((void**)&pdeg, g_deg);

    dim3 gg(2, (NNODES + 127) / 128);

    // 1. node projection -> g_x[:, 0:256]                      (launch 1)
    mma_gemm<<<gg, 256>>>(node_feats, Wnp, bnp, px, NNODES, 256, 128, 128, 512, 0);

    // 2. edge aggregation + edge projection -> g_x[:, 256:512] (launches 2-5)
    zero_kernel<<<((size_t)NNODES * 16 + 255) / 256, 256>>>(pne, (size_t)NNODES * 16);
    zero_kernel<<<(NNODES + 255) / 256, 256>>>(pcnt, NNODES);
    edge_mean_kernel<<<(NEDGES * 16 + 255) / 256, 256>>>(edge_attr, ei);
    nef_kernel<<<NNODES, 256>>>(Wep, bep);

    // 3. GAT1 pre-GEMM (K=512)                                 (launch 6 — profiled)
    mma_gemm<<<gg, 256>>>(px, Wg1, nullptr, pxh, NNODES, 256, 512, 512, 256, 0);

    // 4. CSR build (needed only by gat_fused)
    zero_kernel<<<(NNODES + 255) / 256, 256>>>((float*)pdeg, NNODES);
    hist_kernel<<<(NAUG + 255) / 256, 256>>>(ei);
    scan_kernel<<<1, SCAN_T>>>();
    scatter_kernel<<<(NAUG + 255) / 256, 256>>>(ei);

    // 5. GAT layer 1 sparse part
    att_kernel<<<(NNODES * 4 * 32 + 255) / 256, 256>>>(as1, ad1);
    gat_fused<<<NNODES, 256>>>(bg1, px2);

    // 6. GAT layer 2
    mma_gemm<<<gg, 256>>>(px2, Wg2, nullptr, pxh, NNODES, 256, 256, 256, 256, 0);
    att_kernel<<<(NNODES * 4 * 32 + 255) / 256, 256>>>(as2, ad2);
    gat_fused<<<NNODES, 256>>>(bg2, px2);

    // 7. output projection -> d_out
    mma_gemm<<<gg, 256>>>(px2, Wo, bo, out, NNODES, 256, 256, 256, 256, 0);
}

// round 4
// speedup vs baseline: 1.6590x; 1.6590x over previous
#include <cuda_runtime.h>
#include <math.h>

#define NNODES 50000
#define NEDGES 800000
#define NAUG   (NEDGES + NNODES)   // edges + self loops

// ---------------- scratch (device globals; no allocation allowed) ----------------
__device__ float g_xh  [(size_t)NNODES * 256];   // per-layer head features
__device__ float g_x2  [(size_t)NNODES * 256];   // layer output
__device__ float g_ne  [(size_t)NNODES * 16];    // edge_attr sums
__device__ float g_asrc[NNODES * 4];
__device__ float g_adst[NNODES * 4];
__device__ int   g_deg   [NNODES];
__device__ int   g_rowptr[NNODES + 1];
__device__ int   g_cursor[NNODES];
__device__ int   g_einc  [NAUG];                 // src node per incoming edge (CSR)
__device__ float g_F1[128 * 256];                // Wnp @ Wg1[0:256]
__device__ float g_F2[16 * 256];                 // Wep @ Wg1[256:512]
__device__ float g_cv[256];                      // bnp@Wg1a + bep@Wg1b

// ---------------- helpers ----------------
__device__ __forceinline__ float lrelu(float x) { return x > 0.f ? x : 0.2f * x; }

__device__ __forceinline__ void ffma2(unsigned long long& d, unsigned long long a,
                                      unsigned long long b) {
    asm("fma.rn.f32x2 %0, %1, %2, %0;" : "+l"(d) : "l"(a), "l"(b));
}
__device__ __forceinline__ unsigned long long pack2(float lo, float hi) {
    unsigned long long v;
    asm("mov.b64 %0, {%1, %2};" : "=l"(v) : "r"(__float_as_uint(lo)), "r"(__float_as_uint(hi)));
    return v;
}
__device__ __forceinline__ void unpack2(unsigned long long v, float& lo, float& hi) {
    unsigned int a, b;
    asm("mov.b64 {%0, %1}, %2;" : "=r"(a), "=r"(b) : "l"(v));
    lo = __uint_as_float(a); hi = __uint_as_float(b);
}

// ---------------- generic zero ----------------
__global__ void zero_kernel(float* p, size_t n) {
    size_t i = (size_t)blockIdx.x * blockDim.x + threadIdx.x;
    if (i < n) p[i] = 0.f;
}

// ---------------- SGEMM via packed f32x2: C[M,N] = A[M,K] @ B[K,N] (+bias) ----------------
#define BM 128
#define BN 128
#define BK 16
#define TM 8
#define TN 8
__global__ __launch_bounds__(256) void sgemm_bias(
    const float* __restrict__ A, const float* __restrict__ B,
    const float* __restrict__ bias, float* __restrict__ C,
    int M, int N, int K, int lda, int ldc, int cofs)
{
    __shared__ float As[BK][BM];
    __shared__ float Bs[BK][BN];
    int tid  = threadIdx.x;
    int brow = blockIdx.y, bcol = blockIdx.x;
    int trow = (tid / 16) * TM;
    int tcol = (tid % 16) * TN;
    int arow = tid >> 1;
    int acol = (tid & 1) * 8;
    int browi = tid >> 5;
    int bcoli = (tid & 31) * 4;

    const float* Ablk = A + (size_t)(brow * BM) * lda;
    const float* Bblk = B + bcol * BN;
    unsigned long long acc2[TM][TN / 2] = {};
    int grow_a = brow * BM + arow;

    for (int k0 = 0; k0 < K; k0 += BK) {
        #pragma unroll
        for (int c = 0; c < 2; c++) {
            float4 av = make_float4(0.f, 0.f, 0.f, 0.f);
            if (grow_a < M)
                av = *(const float4*)(Ablk + (size_t)arow * lda + k0 + acol + c * 4);
            As[acol + c * 4 + 0][arow] = av.x;
            As[acol + c * 4 + 1][arow] = av.y;
            As[acol + c * 4 + 2][arow] = av.z;
            As[acol + c * 4 + 3][arow] = av.w;
        }
        #pragma unroll
        for (int c = 0; c < 2; c++) {
            float4 bv = *(const float4*)(Bblk + (size_t)(k0 + browi + c * 8) * N + bcoli);
            *(float4*)&Bs[browi + c * 8][bcoli] = bv;
        }
        __syncthreads();
        #pragma unroll
        for (int kk = 0; kk < BK; kk++) {
            float4 ra0 = *(const float4*)&As[kk][trow];
            float4 ra1 = *(const float4*)&As[kk][trow + 4];
            float ra[TM] = {ra0.x, ra0.y, ra0.z, ra0.w, ra1.x, ra1.y, ra1.z, ra1.w};
            ulonglong2 w0 = *(const ulonglong2*)&Bs[kk][tcol];
            ulonglong2 w1 = *(const ulonglong2*)&Bs[kk][tcol + 4];
            unsigned long long rb2[TN / 2] = {w0.x, w0.y, w1.x, w1.y};
            #pragma unroll
            for (int i = 0; i < TM; i++) {
                unsigned long long a2 = pack2(ra[i], ra[i]);
                #pragma unroll
                for (int j = 0; j < TN / 2; j++) ffma2(acc2[i][j], a2, rb2[j]);
            }
        }
        __syncthreads();
    }
    #pragma unroll
    for (int i = 0; i < TM; i++) {
        int gr = brow * BM + trow + i;
        if (gr >= M) break;
        float accf[TN];
        #pragma unroll
        for (int j = 0; j < TN / 2; j++) unpack2(acc2[i][j], accf[2 * j], accf[2 * j + 1]);
        float* crow = C + (size_t)gr * ldc + cofs + bcol * BN + tcol;
        #pragma unroll
        for (int j = 0; j < TN; j += 4) {
            int gc = bcol * BN + tcol + j;
            float4 v;
            v.x = accf[j + 0] + (bias ? bias[gc + 0] : 0.f);
            v.y = accf[j + 1] + (bias ? bias[gc + 1] : 0.f);
            v.z = accf[j + 2] + (bias ? bias[gc + 2] : 0.f);
            v.w = accf[j + 3] + (bias ? bias[gc + 3] : 0.f);
            *(float4*)(crow + j) = v;
        }
    }
}

// ---------------- weight-fusion precompute ----------------
// out[i][c] = sum_j Wl[i][j] * Wg[j][c], Wl rows = gridDim, 256 cols each
__global__ __launch_bounds__(256) void fuse_w_kernel(const float* __restrict__ Wl,
                                                     const float* __restrict__ Wg,
                                                     float* __restrict__ out) {
    __shared__ float sw[256];
    int i = blockIdx.x, tid = threadIdx.x;
    sw[tid] = Wl[i * 256 + tid];
    __syncthreads();
    float acc = 0.f;
    #pragma unroll 8
    for (int j = 0; j < 256; j++) acc += sw[j] * __ldg(&Wg[j * 256 + tid]);
    out[i * 256 + tid] = acc;
}

// cv[c] = sum_j bnp[j]*Wg1[j][c] + sum_j bep[j]*Wg1[256+j][c]
__global__ __launch_bounds__(256) void fuse_b_kernel(const float* __restrict__ bnp,
                                                     const float* __restrict__ bep,
                                                     const float* __restrict__ Wg1) {
    int tid = threadIdx.x;
    float acc = 0.f;
    #pragma unroll 8
    for (int j = 0; j < 256; j++) acc += __ldg(&bnp[j]) * __ldg(&Wg1[j * 256 + tid]);
    #pragma unroll 8
    for (int j = 0; j < 256; j++) acc += __ldg(&bep[j]) * __ldg(&Wg1[(256 + j) * 256 + tid]);
    g_cv[tid] = acc;
}

// ---------------- scatter sum of edge_attr over dst ----------------
__global__ void edge_mean_kernel(const float* __restrict__ ea, const int* __restrict__ ei) {
    int i = blockIdx.x * blockDim.x + threadIdx.x;
    if (i >= NEDGES * 16) return;
    int e = i >> 4, k = i & 15;
    int d = ei[NEDGES + e];
    atomicAdd(&g_ne[(size_t)d * 16 + k], ea[i]);
}

// ---------------- CSR build ----------------
__global__ void hist_kernel(const int* __restrict__ ei) {
    int e = blockIdx.x * blockDim.x + threadIdx.x;
    if (e >= NAUG) return;
    int d = (e < NEDGES) ? ei[NEDGES + e] : e - NEDGES;
    atomicAdd(&g_deg[d], 1);
}

#define SCAN_T 1024
__global__ __launch_bounds__(SCAN_T) void scan_kernel() {
    __shared__ int part[SCAN_T];
    int t = threadIdx.x;
    const int CH = (NNODES + SCAN_T - 1) / SCAN_T;
    int base = t * CH;
    int sum = 0;
    for (int i = 0; i < CH; i++) {
        int idx = base + i;
        if (idx < NNODES) sum += g_deg[idx];
    }
    part[t] = sum;
    __syncthreads();
    for (int off = 1; off < SCAN_T; off <<= 1) {
        int v = (t >= off) ? part[t - off] : 0;
        __syncthreads();
        part[t] += v;
        __syncthreads();
    }
    int run = part[t] - sum;
    for (int i = 0; i < CH; i++) {
        int idx = base + i;
        if (idx < NNODES) {
            g_rowptr[idx] = run;
            g_cursor[idx] = run;
            run += g_deg[idx];
        }
    }
    if (t == SCAN_T - 1) g_rowptr[NNODES] = NAUG;
}

__global__ void scatter_kernel(const int* __restrict__ ei) {
    int e = blockIdx.x * blockDim.x + threadIdx.x;
    if (e >= NAUG) return;
    int s, d;
    if (e < NEDGES) { s = ei[e]; d = ei[NEDGES + e]; }
    else            { s = d = e - NEDGES; }
    int pos = atomicAdd(&g_cursor[d], 1);
    g_einc[pos] = s;
}

// ---------------- rank-16 update: xh += nefmean @ F2 + cvec ----------------
#define NPB 8
__global__ __launch_bounds__(256) void rank16_kernel() {
    __shared__ float sF2[16 * 256];
    __shared__ float sne[NPB * 16];
    int tid = threadIdx.x;
    int nb = blockIdx.x * NPB;
    #pragma unroll
    for (int i = 0; i < 16; i++) sF2[i * 256 + tid] = g_F2[i * 256 + tid];
    if (tid < NPB * 16) {
        int node = nb + tid / 16, k = tid & 15;
        if (node < NNODES) {
            int cnt = g_rowptr[node + 1] - g_rowptr[node] - 1;  // real in-edges
            float c = cnt < 1 ? 1.f : (float)cnt;
            sne[tid] = g_ne[(size_t)node * 16 + k] / c;
        }
    }
    __syncthreads();
    float cv = g_cv[tid];
    #pragma unroll
    for (int i = 0; i < NPB; i++) {
        int node = nb + i;
        if (node >= NNODES) break;
        float acc = cv;
        #pragma unroll
        for (int k = 0; k < 16; k++) acc += sne[i * 16 + k] * sF2[k * 256 + tid];
        g_xh[(size_t)node * 256 + tid] += acc;
    }
}

// ---------------- per-node attention coefficients ----------------
__global__ void att_kernel(const float* __restrict__ as, const float* __restrict__ ad) {
    int w = (blockIdx.x * blockDim.x + threadIdx.x) >> 5;
    int lane = threadIdx.x & 31;
    if (w >= NNODES * 4) return;
    int node = w >> 2, h = w & 3;
    const float* xr = g_xh + (size_t)node * 256 + h * 64;
    float s1 = xr[lane] * as[h * 64 + lane] + xr[lane + 32] * as[h * 64 + lane + 32];
    float s2 = xr[lane] * ad[h * 64 + lane] + xr[lane + 32] * ad[h * 64 + lane + 32];
    #pragma unroll
    for (int o = 16; o; o >>= 1) {
        s1 += __shfl_down_sync(0xffffffffu, s1, o);
        s2 += __shfl_down_sync(0xffffffffu, s2, o);
    }
    if (lane == 0) {
        g_asrc[w] = s1;
        g_adst[w] = s2;
    }
}

// ---------------- fused GAT: online softmax + gather-aggregate + bias + ELU ----------------
__global__ __launch_bounds__(256) void gat_fused(const float* __restrict__ bias,
                                                 float* __restrict__ out) {
    __shared__ float sm[256];
    __shared__ float sd[256];
    int node = blockIdx.x;
    int tid = threadIdx.x;
    int beg = g_rowptr[node], end = g_rowptr[node + 1];
    int deg = end - beg;

    // Phase 1: online softmax stats. thread = (e-slot, head)
    int h = tid & 3;
    int es = tid >> 2;
    float adst = g_adst[node * 4 + h];
    float m = -INFINITY, dsum = 0.f;
    for (int i = es; i < deg; i += 64) {
        int s = g_einc[beg + i];
        float l = lrelu(g_asrc[s * 4 + h] + adst);
        if (l > m) { dsum = dsum * __expf(m - l) + 1.f; m = l; }
        else       { dsum += __expf(l - m); }
    }
    sm[tid] = m; sd[tid] = dsum;
    __syncthreads();
    #pragma unroll
    for (int s = 32; s >= 1; s >>= 1) {
        if (es < s) {
            float m1 = sm[tid], d1 = sd[tid];
            float m2 = sm[tid + 4 * s], d2 = sd[tid + 4 * s];
            float M = fmaxf(m1, m2);
            float e1 = (m1 == -INFINITY) ? 0.f : __expf(m1 - M);
            float e2 = (m2 == -INFINITY) ? 0.f : __expf(m2 - M);
            sm[tid] = M;
            sd[tid] = d1 * e1 + d2 * e2;
        }
        __syncthreads();
    }

    // Phase 2: aggregate. thread = feature; head = tid>>6
    int h2 = tid >> 6;
    float M = sm[h2];
    float Dinv = 1.f / sd[h2];
    float adst2 = g_adst[node * 4 + h2];
    float acc = 0.f;
    for (int e = beg; e < end; e++) {
        int s = g_einc[e];
        float l = lrelu(g_asrc[s * 4 + h2] + adst2);
        float alpha = __expf(l - M) * Dinv;
        acc += alpha * g_xh[(size_t)s * 256 + tid];
    }
    float v = acc + bias[tid];
    out[(size_t)node * 256 + tid] = v > 0.f ? v : expm1f(v);
}

// ---------------- host launch ----------------
extern "C" void kernel_launch(void* const* d_in, const int* in_sizes, int n_in,
                              void* d_out, int out_size) {
    const float* node_feats = (const float*)d_in[0];
    const float* edge_attr  = (const float*)d_in[1];
    const float* Wnp = (const float*)d_in[2];
    const float* bnp = (const float*)d_in[3];
    const float* Wep = (const float*)d_in[4];
    const float* bep = (const float*)d_in[5];
    const float* Wg1 = (const float*)d_in[6];
    const float* as1 = (const float*)d_in[7];
    const float* ad1 = (const float*)d_in[8];
    const float* bg1 = (const float*)d_in[9];
    const float* Wg2 = (const float*)d_in[10];
    const float* as2 = (const float*)d_in[11];
    const float* ad2 = (const float*)d_in[12];
    const float* bg2 = (const float*)d_in[13];
    const float* Wo  = (const float*)d_in[14];
    const float* bo  = (const float*)d_in[15];
    const int*   ei  = (const int*)d_in[16];
    float* out = (float*)d_out;

    float *pxh, *px2, *pne, *pF1, *pF2;
    int* pdeg;
    cudaGetSymbolAddress((void**)&pxh,  g_xh);
    cudaGetSymbolAddress((void**)&px2,  g_x2);
    cudaGetSymbolAddress((void**)&pne,  g_ne);
    cudaGetSymbolAddress((void**)&pF1,  g_F1);
    cudaGetSymbolAddress((void**)&pF2,  g_F2);
    cudaGetSymbolAddress((void**)&pdeg, g_deg);

    dim3 gg(2, (NNODES + BM - 1) / BM);

    // 1-3. weight fusion precompute
    fuse_w_kernel<<<128, 256>>>(Wnp, Wg1, pF1);                 // F1 = Wnp @ Wg1a
    fuse_w_kernel<<<16, 256>>>(Wep, Wg1 + 256 * 256, pF2);      // F2 = Wep @ Wg1b
    fuse_b_kernel<<<1, 256>>>(bnp, bep, Wg1);                   // cvec

    // 4. main fused GEMM: xh = node_feats @ F1   (PROFILED SLOT)
    sgemm_bias<<<gg, 256>>>(node_feats, pF1, nullptr, pxh, NNODES, 256, 128, 128, 256, 0);

    // 5-6. edge_attr scatter-sum
    zero_kernel<<<((size_t)NNODES * 16 + 255) / 256, 256>>>(pne, (size_t)NNODES * 16);
    edge_mean_kernel<<<(NEDGES * 16 + 255) / 256, 256>>>(edge_attr, ei);

    // 7-10. CSR build
    zero_kernel<<<(NNODES + 255) / 256, 256>>>((float*)pdeg, NNODES);
    hist_kernel<<<(NAUG + 255) / 256, 256>>>(ei);
    scan_kernel<<<1, SCAN_T>>>();
    scatter_kernel<<<(NAUG + 255) / 256, 256>>>(ei);

    // 11. xh += nefmean @ F2 + cvec
    rank16_kernel<<<(NNODES + NPB - 1) / NPB, 256>>>();

    // 12-13. GAT layer 1 sparse part -> g_x2
    att_kernel<<<(NNODES * 4 * 32 + 255) / 256, 256>>>(as1, ad1);
    gat_fused<<<NNODES, 256>>>(bg1, px2);

    // 14-16. GAT layer 2
    sgemm_bias<<<gg, 256>>>(px2, Wg2, nullptr, pxh, NNODES, 256, 256, 256, 256, 0);
    att_kernel<<<(NNODES * 4 * 32 + 255) / 256, 256>>>(as2, ad2);
    gat_fused<<<NNODES, 256>>>(bg2, px2);

    // 17. output projection -> d_out
    sgemm_bias<<<gg, 256>>>(px2, Wo, bo, out, NNODES, 256, 256, 256, 256, 0);
}

// round 5
// speedup vs baseline: 1.7469x; 1.0530x over previous
#include <cuda_runtime.h>
#include <math.h>

#define NNODES 50000
#define NEDGES 800000
#define NAUG   (NEDGES + NNODES)   // edges + self loops

// ---------------- scratch (device globals; no allocation allowed) ----------------
__device__ float g_xh  [(size_t)NNODES * 256];   // per-layer head features
__device__ float g_x2  [(size_t)NNODES * 256];   // layer output
__device__ float g_ne  [(size_t)NNODES * 16];    // edge_attr sums
__device__ float g_asrc[NNODES * 4];
__device__ float g_adst[NNODES * 4];
__device__ int   g_deg   [NNODES];
__device__ int   g_rowptr[NNODES + 1];
__device__ int   g_cursor[NNODES];
__device__ int   g_einc  [NAUG];                 // src node per incoming edge (CSR)
__device__ float g_F1[128 * 256];                // Wnp @ Wg1[0:256]
__device__ float g_F2[16 * 256];                 // Wep @ Wg1[256:512]
__device__ float g_cv[256];                      // bnp@Wg1a + bep@Wg1b

// ---------------- helpers ----------------
__device__ __forceinline__ float lrelu(float x) { return x > 0.f ? x : 0.2f * x; }

__device__ __forceinline__ void ffma2(unsigned long long& d, unsigned long long a,
                                      unsigned long long b) {
    asm("fma.rn.f32x2 %0, %1, %2, %0;" : "+l"(d) : "l"(a), "l"(b));
}
__device__ __forceinline__ unsigned long long pack2(float lo, float hi) {
    unsigned long long v;
    asm("mov.b64 %0, {%1, %2};" : "=l"(v) : "r"(__float_as_uint(lo)), "r"(__float_as_uint(hi)));
    return v;
}
__device__ __forceinline__ void unpack2(unsigned long long v, float& lo, float& hi) {
    unsigned int a, b;
    asm("mov.b64 {%0, %1}, %2;" : "=r"(a), "=r"(b) : "l"(v));
    lo = __uint_as_float(a); hi = __uint_as_float(b);
}

// ---------------- zero helpers ----------------
__global__ void zero2_kernel(float* p1, size_t n1, int* p2, size_t n2) {
    size_t i = (size_t)blockIdx.x * blockDim.x + threadIdx.x;
    if (i < n1) p1[i] = 0.f;
    if (i < n2) p2[i] = 0;
}

// ---------------- SGEMM via packed f32x2, conflict-free LDS ----------------
// Thread tile: 8 rows x (4 + 4) cols, second col chunk at +64.
#define BM 128
#define BN 128
#define BK 16
#define TM 8
__global__ __launch_bounds__(256) void sgemm_bias(
    const float* __restrict__ A, const float* __restrict__ B,
    const float* __restrict__ bias, float* __restrict__ C,
    int M, int N, int K, int lda, int ldc, int cofs)
{
    __shared__ float As[BK][BM];
    __shared__ float Bs[BK][BN];
    int tid  = threadIdx.x;
    int brow = blockIdx.y, bcol = blockIdx.x;
    int trow = (tid / 16) * TM;
    int n0   = (tid % 16) * 4;        // cols n0..n0+3 and n0+64..n0+67
    int arow = tid >> 1;
    int acol = (tid & 1) * 8;
    int browi = tid >> 5;
    int bcoli = (tid & 31) * 4;

    const float* Ablk = A + (size_t)(brow * BM) * lda;
    const float* Bblk = B + bcol * BN;
    unsigned long long acc2[TM][4] = {};
    int grow_a = brow * BM + arow;

    for (int k0 = 0; k0 < K; k0 += BK) {
        #pragma unroll
        for (int c = 0; c < 2; c++) {
            float4 av = make_float4(0.f, 0.f, 0.f, 0.f);
            if (grow_a < M)
                av = *(const float4*)(Ablk + (size_t)arow * lda + k0 + acol + c * 4);
            As[acol + c * 4 + 0][arow] = av.x;
            As[acol + c * 4 + 1][arow] = av.y;
            As[acol + c * 4 + 2][arow] = av.z;
            As[acol + c * 4 + 3][arow] = av.w;
        }
        #pragma unroll
        for (int c = 0; c < 2; c++) {
            float4 bv = *(const float4*)(Bblk + (size_t)(k0 + browi + c * 8) * N + bcoli);
            *(float4*)&Bs[browi + c * 8][bcoli] = bv;
        }
        __syncthreads();
        #pragma unroll
        for (int kk = 0; kk < BK; kk++) {
            float4 ra0 = *(const float4*)&As[kk][trow];
            float4 ra1 = *(const float4*)&As[kk][trow + 4];
            float ra[TM] = {ra0.x, ra0.y, ra0.z, ra0.w, ra1.x, ra1.y, ra1.z, ra1.w};
            // conflict-free: 8 lanes/phase cover 128B contiguous
            ulonglong2 w0 = *(const ulonglong2*)&Bs[kk][n0];
            ulonglong2 w1 = *(const ulonglong2*)&Bs[kk][n0 + 64];
            unsigned long long rb2[4] = {w0.x, w0.y, w1.x, w1.y};
            #pragma unroll
            for (int i = 0; i < TM; i++) {
                unsigned long long a2 = pack2(ra[i], ra[i]);
                #pragma unroll
                for (int j = 0; j < 4; j++) ffma2(acc2[i][j], a2, rb2[j]);
            }
        }
        __syncthreads();
    }
    #pragma unroll
    for (int i = 0; i < TM; i++) {
        int gr = brow * BM + trow + i;
        if (gr >= M) break;
        float accf[8];
        #pragma unroll
        for (int j = 0; j < 4; j++) unpack2(acc2[i][j], accf[2 * j], accf[2 * j + 1]);
        float* crow = C + (size_t)gr * ldc + cofs + bcol * BN;
        #pragma unroll
        for (int half = 0; half < 2; half++) {
            int gc = n0 + half * 64;
            int bc = bcol * BN + gc;
            float4 v;
            v.x = accf[half * 4 + 0] + (bias ? bias[bc + 0] : 0.f);
            v.y = accf[half * 4 + 1] + (bias ? bias[bc + 1] : 0.f);
            v.z = accf[half * 4 + 2] + (bias ? bias[bc + 2] : 0.f);
            v.w = accf[half * 4 + 3] + (bias ? bias[bc + 3] : 0.f);
            *(float4*)(crow + gc) = v;
        }
    }
}

// ---------------- weight-fusion precompute ----------------
__global__ __launch_bounds__(256) void fuse_w_kernel(const float* __restrict__ Wl,
                                                     const float* __restrict__ Wg,
                                                     float* __restrict__ out) {
    __shared__ float sw[256];
    int i = blockIdx.x, tid = threadIdx.x;
    sw[tid] = Wl[i * 256 + tid];
    __syncthreads();
    float acc = 0.f;
    #pragma unroll 8
    for (int j = 0; j < 256; j++) acc += sw[j] * __ldg(&Wg[j * 256 + tid]);
    out[i * 256 + tid] = acc;
}

__global__ __launch_bounds__(256) void fuse_b_kernel(const float* __restrict__ bnp,
                                                     const float* __restrict__ bep,
                                                     const float* __restrict__ Wg1) {
    int tid = threadIdx.x;
    float acc = 0.f;
    #pragma unroll 8
    for (int j = 0; j < 256; j++) acc += __ldg(&bnp[j]) * __ldg(&Wg1[j * 256 + tid]);
    #pragma unroll 8
    for (int j = 0; j < 256; j++) acc += __ldg(&bep[j]) * __ldg(&Wg1[(256 + j) * 256 + tid]);
    g_cv[tid] = acc;
}

// ---------------- scatter sum of edge_attr over dst ----------------
__global__ void edge_mean_kernel(const float* __restrict__ ea, const int* __restrict__ ei) {
    int i = blockIdx.x * blockDim.x + threadIdx.x;
    if (i >= NEDGES * 16) return;
    int e = i >> 4, k = i & 15;
    int d = ei[NEDGES + e];
    atomicAdd(&g_ne[(size_t)d * 16 + k], ea[i]);
}

// ---------------- CSR build ----------------
__global__ void hist_kernel(const int* __restrict__ ei) {
    int e = blockIdx.x * blockDim.x + threadIdx.x;
    if (e >= NAUG) return;
    int d = (e < NEDGES) ? ei[NEDGES + e] : e - NEDGES;
    atomicAdd(&g_deg[d], 1);
}

#define SCAN_T 1024
__global__ __launch_bounds__(SCAN_T) void scan_kernel() {
    __shared__ int part[SCAN_T];
    int t = threadIdx.x;
    const int CH = (NNODES + SCAN_T - 1) / SCAN_T;
    int base = t * CH;
    int sum = 0;
    for (int i = 0; i < CH; i++) {
        int idx = base + i;
        if (idx < NNODES) sum += g_deg[idx];
    }
    part[t] = sum;
    __syncthreads();
    for (int off = 1; off < SCAN_T; off <<= 1) {
        int v = (t >= off) ? part[t - off] : 0;
        __syncthreads();
        part[t] += v;
        __syncthreads();
    }
    int run = part[t] - sum;
    for (int i = 0; i < CH; i++) {
        int idx = base + i;
        if (idx < NNODES) {
            g_rowptr[idx] = run;
            g_cursor[idx] = run;
            run += g_deg[idx];
        }
    }
    if (t == SCAN_T - 1) g_rowptr[NNODES] = NAUG;
}

__global__ void scatter_kernel(const int* __restrict__ ei) {
    int e = blockIdx.x * blockDim.x + threadIdx.x;
    if (e >= NAUG) return;
    int s, d;
    if (e < NEDGES) { s = ei[e]; d = ei[NEDGES + e]; }
    else            { s = d = e - NEDGES; }
    int pos = atomicAdd(&g_cursor[d], 1);
    g_einc[pos] = s;
}

// ---------------- rank-16 update: xh += nefmean @ F2 + cvec ----------------
#define NPB 8
__global__ __launch_bounds__(256) void rank16_kernel() {
    __shared__ float sF2[16 * 256];
    __shared__ float sne[NPB * 16];
    int tid = threadIdx.x;
    int nb = blockIdx.x * NPB;
    #pragma unroll
    for (int i = 0; i < 16; i++) sF2[i * 256 + tid] = g_F2[i * 256 + tid];
    if (tid < NPB * 16) {
        int node = nb + tid / 16, k = tid & 15;
        if (node < NNODES) {
            int cnt = g_rowptr[node + 1] - g_rowptr[node] - 1;  // real in-edges
            float c = cnt < 1 ? 1.f : (float)cnt;
            sne[tid] = g_ne[(size_t)node * 16 + k] / c;
        }
    }
    __syncthreads();
    float cv = g_cv[tid];
    #pragma unroll
    for (int i = 0; i < NPB; i++) {
        int node = nb + i;
        if (node >= NNODES) break;
        float acc = cv;
        #pragma unroll
        for (int k = 0; k < 16; k++) acc += sne[i * 16 + k] * sF2[k * 256 + tid];
        g_xh[(size_t)node * 256 + tid] += acc;
    }
}

// ---------------- per-node attention coefficients ----------------
__global__ void att_kernel(const float* __restrict__ as, const float* __restrict__ ad) {
    int w = (blockIdx.x * blockDim.x + threadIdx.x) >> 5;
    int lane = threadIdx.x & 31;
    if (w >= NNODES * 4) return;
    int node = w >> 2, h = w & 3;
    const float* xr = g_xh + (size_t)node * 256 + h * 64;
    float s1 = xr[lane] * as[h * 64 + lane] + xr[lane + 32] * as[h * 64 + lane + 32];
    float s2 = xr[lane] * ad[h * 64 + lane] + xr[lane + 32] * ad[h * 64 + lane + 32];
    #pragma unroll
    for (int o = 16; o; o >>= 1) {
        s1 += __shfl_down_sync(0xffffffffu, s1, o);
        s2 += __shfl_down_sync(0xffffffffu, s2, o);
    }
    if (lane == 0) {
        g_asrc[w] = s1;
        g_adst[w] = s2;
    }
}

// ---------------- fused GAT: online softmax + gather-aggregate + bias + ELU ----------------
__global__ __launch_bounds__(256) void gat_fused(const float* __restrict__ bias,
                                                 float* __restrict__ out) {
    __shared__ float sm[256];
    __shared__ float sd[256];
    int node = blockIdx.x;
    int tid = threadIdx.x;
    int beg = g_rowptr[node], end = g_rowptr[node + 1];
    int deg = end - beg;

    // Phase 1: online softmax stats. thread = (e-slot, head)
    int h = tid & 3;
    int es = tid >> 2;
    float adst = g_adst[node * 4 + h];
    float m = -INFINITY, dsum = 0.f;
    for (int i = es; i < deg; i += 64) {
        int s = g_einc[beg + i];
        float l = lrelu(g_asrc[s * 4 + h] + adst);
        if (l > m) { dsum = dsum * __expf(m - l) + 1.f; m = l; }
        else       { dsum += __expf(l - m); }
    }
    sm[tid] = m; sd[tid] = dsum;
    __syncthreads();
    #pragma unroll
    for (int s = 32; s >= 1; s >>= 1) {
        if (es < s) {
            float m1 = sm[tid], d1 = sd[tid];
            float m2 = sm[tid + 4 * s], d2 = sd[tid + 4 * s];
            float M = fmaxf(m1, m2);
            float e1 = (m1 == -INFINITY) ? 0.f : __expf(m1 - M);
            float e2 = (m2 == -INFINITY) ? 0.f : __expf(m2 - M);
            sm[tid] = M;
            sd[tid] = d1 * e1 + d2 * e2;
        }
        __syncthreads();
    }

    // Phase 2: aggregate with 2-wide unroll (MLP=2). thread = feature; head = tid>>6
    int h2 = tid >> 6;
    float M = sm[h2];
    float Dinv = 1.f / sd[h2];
    float adst2 = g_adst[node * 4 + h2];
    float acc = 0.f;
    int e = beg;
    for (; e + 2 <= end; e += 2) {
        int s0 = g_einc[e], s1 = g_einc[e + 1];
        float x0 = g_xh[(size_t)s0 * 256 + tid];
        float x1 = g_xh[(size_t)s1 * 256 + tid];
        float l0 = lrelu(g_asrc[s0 * 4 + h2] + adst2);
        float l1 = lrelu(g_asrc[s1 * 4 + h2] + adst2);
        acc += __expf(l0 - M) * Dinv * x0;
        acc += __expf(l1 - M) * Dinv * x1;
    }
    if (e < end) {
        int s0 = g_einc[e];
        float l0 = lrelu(g_asrc[s0 * 4 + h2] + adst2);
        acc += __expf(l0 - M) * Dinv * g_xh[(size_t)s0 * 256 + tid];
    }
    float v = acc + bias[tid];
    out[(size_t)node * 256 + tid] = v > 0.f ? v : expm1f(v);
}

// ---------------- host launch ----------------
extern "C" void kernel_launch(void* const* d_in, const int* in_sizes, int n_in,
                              void* d_out, int out_size) {
    const float* node_feats = (const float*)d_in[0];
    const float* edge_attr  = (const float*)d_in[1];
    const float* Wnp = (const float*)d_in[2];
    const float* bnp = (const float*)d_in[3];
    const float* Wep = (const float*)d_in[4];
    const float* bep = (const float*)d_in[5];
    const float* Wg1 = (const float*)d_in[6];
    const float* as1 = (const float*)d_in[7];
    const float* ad1 = (const float*)d_in[8];
    const float* bg1 = (const float*)d_in[9];
    const float* Wg2 = (const float*)d_in[10];
    const float* as2 = (const float*)d_in[11];
    const float* ad2 = (const float*)d_in[12];
    const float* bg2 = (const float*)d_in[13];
    const float* Wo  = (const float*)d_in[14];
    const float* bo  = (const float*)d_in[15];
    const int*   ei  = (const int*)d_in[16];
    float* out = (float*)d_out;

    float *pxh, *px2, *pne, *pF1, *pF2;
    int* pdeg;
    cudaGetSymbolAddress((void**)&pxh,  g_xh);
    cudaGetSymbolAddress((void**)&px2,  g_x2);
    cudaGetSymbolAddress((void**)&pne,  g_ne);
    cudaGetSymbolAddress((void**)&pF1,  g_F1);
    cudaGetSymbolAddress((void**)&pF2,  g_F2);
    cudaGetSymbolAddress((void**)&pdeg, g_deg);

    dim3 gg(2, (NNODES + BM - 1) / BM);

    // 1-3. weight fusion precompute
    fuse_w_kernel<<<128, 256>>>(Wnp, Wg1, pF1);
    fuse_w_kernel<<<16, 256>>>(Wep, Wg1 + 256 * 256, pF2);
    fuse_b_kernel<<<1, 256>>>(bnp, bep, Wg1);

    // 4. main fused GEMM: xh = node_feats @ F1   (PROFILED SLOT)
    sgemm_bias<<<gg, 256>>>(node_feats, pF1, nullptr, pxh, NNODES, 256, 128, 128, 256, 0);

    // 5-6. edge_attr scatter-sum (+ deg zero fused)
    zero2_kernel<<<((size_t)NNODES * 16 + 255) / 256, 256>>>(pne, (size_t)NNODES * 16,
                                                             pdeg, NNODES);
    edge_mean_kernel<<<(NEDGES * 16 + 255) / 256, 256>>>(edge_attr, ei);

    // 7-9. CSR build
    hist_kernel<<<(NAUG + 255) / 256, 256>>>(ei);
    scan_kernel<<<1, SCAN_T>>>();
    scatter_kernel<<<(NAUG + 255) / 256, 256>>>(ei);

    // 10. xh += nefmean @ F2 + cvec
    rank16_kernel<<<(NNODES + NPB - 1) / NPB, 256>>>();

    // 11-12. GAT layer 1 sparse part -> g_x2
    att_kernel<<<(NNODES * 4 * 32 + 255) / 256, 256>>>(as1, ad1);
    gat_fused<<<NNODES, 256>>>(bg1, px2);

    // 13-15. GAT layer 2
    sgemm_bias<<<gg, 256>>>(px2, Wg2, nullptr, pxh, NNODES, 256, 256, 256, 256, 0);
    att_kernel<<<(NNODES * 4 * 32 + 255) / 256, 256>>>(as2, ad2);
    gat_fused<<<NNODES, 256>>>(bg2, px2);

    // 16. output projection -> d_out
    sgemm_bias<<<gg, 256>>>(px2, Wo, bo, out, NNODES, 256, 256, 256, 256, 0);
}

// round 6
// speedup vs baseline: 2.2561x; 1.2915x over previous
#include <cuda_runtime.h>
#include <math.h>

#define NNODES 50000
#define NEDGES 800000
#define NAUG   (NEDGES + NNODES)   // edges + self loops

// ---------------- scratch (device globals; no allocation allowed) ----------------
__device__ float g_xh  [(size_t)NNODES * 256];   // per-layer head features
__device__ float g_x2  [(size_t)NNODES * 256];   // layer output
__device__ float g_ne  [(size_t)NNODES * 16];    // edge_attr sums
__device__ float g_asrc[NNODES * 4];
__device__ float g_adst[NNODES * 4];
__device__ int   g_deg   [NNODES];
__device__ int   g_rowptr[NNODES + 1];
__device__ int   g_cursor[NNODES];
__device__ int   g_einc  [NAUG];                 // src node per incoming edge (CSR)
__device__ float g_F1[128 * 256];                // Wnp @ Wg1[0:256]
__device__ float g_F2[16 * 256];                 // Wep @ Wg1[256:512]
__device__ float g_cv[256];                      // bnp@Wg1a + bep@Wg1b

// ---------------- helpers ----------------
__device__ __forceinline__ float lrelu(float x) { return x > 0.f ? x : 0.2f * x; }

__device__ __forceinline__ void ffma2(unsigned long long& d, unsigned long long a,
                                      unsigned long long b) {
    asm("fma.rn.f32x2 %0, %1, %2, %0;" : "+l"(d) : "l"(a), "l"(b));
}
__device__ __forceinline__ unsigned long long pack2(float lo, float hi) {
    unsigned long long v;
    asm("mov.b64 %0, {%1, %2};" : "=l"(v) : "r"(__float_as_uint(lo)), "r"(__float_as_uint(hi)));
    return v;
}
__device__ __forceinline__ void unpack2(unsigned long long v, float& lo, float& hi) {
    unsigned int a, b;
    asm("mov.b64 {%0, %1}, %2;" : "=r"(a), "=r"(b) : "l"(v));
    lo = __uint_as_float(a); hi = __uint_as_float(b);
}

// ---------------- zero helpers ----------------
__global__ void zero2_kernel(float* p1, size_t n1, int* p2, size_t n2) {
    size_t i = (size_t)blockIdx.x * blockDim.x + threadIdx.x;
    if (i < n1) p1[i] = 0.f;
    if (i < n2) p2[i] = 0;
}

// ---------------- SGEMM via packed f32x2, conflict-free LDS ----------------
#define BM 128
#define BN 128
#define BK 16
#define TM 8
__global__ __launch_bounds__(256) void sgemm_bias(
    const float* __restrict__ A, const float* __restrict__ B,
    const float* __restrict__ bias, float* __restrict__ C,
    int M, int N, int K, int lda, int ldc, int cofs)
{
    __shared__ float As[BK][BM];
    __shared__ float Bs[BK][BN];
    int tid  = threadIdx.x;
    int brow = blockIdx.y, bcol = blockIdx.x;
    int trow = (tid / 16) * TM;
    int n0   = (tid % 16) * 4;
    int arow = tid >> 1;
    int acol = (tid & 1) * 8;
    int browi = tid >> 5;
    int bcoli = (tid & 31) * 4;

    const float* Ablk = A + (size_t)(brow * BM) * lda;
    const float* Bblk = B + bcol * BN;
    unsigned long long acc2[TM][4] = {};
    int grow_a = brow * BM + arow;

    for (int k0 = 0; k0 < K; k0 += BK) {
        #pragma unroll
        for (int c = 0; c < 2; c++) {
            float4 av = make_float4(0.f, 0.f, 0.f, 0.f);
            if (grow_a < M)
                av = *(const float4*)(Ablk + (size_t)arow * lda + k0 + acol + c * 4);
            As[acol + c * 4 + 0][arow] = av.x;
            As[acol + c * 4 + 1][arow] = av.y;
            As[acol + c * 4 + 2][arow] = av.z;
            As[acol + c * 4 + 3][arow] = av.w;
        }
        #pragma unroll
        for (int c = 0; c < 2; c++) {
            float4 bv = *(const float4*)(Bblk + (size_t)(k0 + browi + c * 8) * N + bcoli);
            *(float4*)&Bs[browi + c * 8][bcoli] = bv;
        }
        __syncthreads();
        #pragma unroll
        for (int kk = 0; kk < BK; kk++) {
            float4 ra0 = *(const float4*)&As[kk][trow];
            float4 ra1 = *(const float4*)&As[kk][trow + 4];
            float ra[TM] = {ra0.x, ra0.y, ra0.z, ra0.w, ra1.x, ra1.y, ra1.z, ra1.w};
            ulonglong2 w0 = *(const ulonglong2*)&Bs[kk][n0];
            ulonglong2 w1 = *(const ulonglong2*)&Bs[kk][n0 + 64];
            unsigned long long rb2[4] = {w0.x, w0.y, w1.x, w1.y};
            #pragma unroll
            for (int i = 0; i < TM; i++) {
                unsigned long long a2 = pack2(ra[i], ra[i]);
                #pragma unroll
                for (int j = 0; j < 4; j++) ffma2(acc2[i][j], a2, rb2[j]);
            }
        }
        __syncthreads();
    }
    #pragma unroll
    for (int i = 0; i < TM; i++) {
        int gr = brow * BM + trow + i;
        if (gr >= M) break;
        float accf[8];
        #pragma unroll
        for (int j = 0; j < 4; j++) unpack2(acc2[i][j], accf[2 * j], accf[2 * j + 1]);
        float* crow = C + (size_t)gr * ldc + cofs + bcol * BN;
        #pragma unroll
        for (int half = 0; half < 2; half++) {
            int gc = n0 + half * 64;
            int bc = bcol * BN + gc;
            float4 v;
            v.x = accf[half * 4 + 0] + (bias ? bias[bc + 0] : 0.f);
            v.y = accf[half * 4 + 1] + (bias ? bias[bc + 1] : 0.f);
            v.z = accf[half * 4 + 2] + (bias ? bias[bc + 2] : 0.f);
            v.w = accf[half * 4 + 3] + (bias ? bias[bc + 3] : 0.f);
            *(float4*)(crow + gc) = v;
        }
    }
}

// ---------------- weight-fusion precompute ----------------
__global__ __launch_bounds__(256) void fuse_w_kernel(const float* __restrict__ Wl,
                                                     const float* __restrict__ Wg,
                                                     float* __restrict__ out) {
    __shared__ float sw[256];
    int i = blockIdx.x, tid = threadIdx.x;
    sw[tid] = Wl[i * 256 + tid];
    __syncthreads();
    float acc = 0.f;
    #pragma unroll 8
    for (int j = 0; j < 256; j++) acc += sw[j] * __ldg(&Wg[j * 256 + tid]);
    out[i * 256 + tid] = acc;
}

__global__ __launch_bounds__(256) void fuse_b_kernel(const float* __restrict__ bnp,
                                                     const float* __restrict__ bep,
                                                     const float* __restrict__ Wg1) {
    int tid = threadIdx.x;
    float acc = 0.f;
    #pragma unroll 8
    for (int j = 0; j < 256; j++) acc += __ldg(&bnp[j]) * __ldg(&Wg1[j * 256 + tid]);
    #pragma unroll 8
    for (int j = 0; j < 256; j++) acc += __ldg(&bep[j]) * __ldg(&Wg1[(256 + j) * 256 + tid]);
    g_cv[tid] = acc;
}

// ---------------- scatter sum of edge_attr over dst ----------------
__global__ void edge_mean_kernel(const float* __restrict__ ea, const int* __restrict__ ei) {
    int i = blockIdx.x * blockDim.x + threadIdx.x;
    if (i >= NEDGES * 16) return;
    int e = i >> 4, k = i & 15;
    int d = ei[NEDGES + e];
    atomicAdd(&g_ne[(size_t)d * 16 + k], ea[i]);
}

// ---------------- CSR build ----------------
__global__ void hist_kernel(const int* __restrict__ ei) {
    int e = blockIdx.x * blockDim.x + threadIdx.x;
    if (e >= NAUG) return;
    int d = (e < NEDGES) ? ei[NEDGES + e] : e - NEDGES;
    atomicAdd(&g_deg[d], 1);
}

#define SCAN_T 1024
__global__ __launch_bounds__(SCAN_T) void scan_kernel() {
    __shared__ int part[SCAN_T];
    int t = threadIdx.x;
    const int CH = (NNODES + SCAN_T - 1) / SCAN_T;
    int base = t * CH;
    int sum = 0;
    for (int i = 0; i < CH; i++) {
        int idx = base + i;
        if (idx < NNODES) sum += g_deg[idx];
    }
    part[t] = sum;
    __syncthreads();
    for (int off = 1; off < SCAN_T; off <<= 1) {
        int v = (t >= off) ? part[t - off] : 0;
        __syncthreads();
        part[t] += v;
        __syncthreads();
    }
    int run = part[t] - sum;
    for (int i = 0; i < CH; i++) {
        int idx = base + i;
        if (idx < NNODES) {
            g_rowptr[idx] = run;
            g_cursor[idx] = run;
            run += g_deg[idx];
        }
    }
    if (t == SCAN_T - 1) g_rowptr[NNODES] = NAUG;
}

__global__ void scatter_kernel(const int* __restrict__ ei) {
    int e = blockIdx.x * blockDim.x + threadIdx.x;
    if (e >= NAUG) return;
    int s, d;
    if (e < NEDGES) { s = ei[e]; d = ei[NEDGES + e]; }
    else            { s = d = e - NEDGES; }
    int pos = atomicAdd(&g_cursor[d], 1);
    g_einc[pos] = s;
}

// ---------------- rank-16 update: xh += nefmean @ F2 + cvec ----------------
#define NPB 8
__global__ __launch_bounds__(256) void rank16_kernel() {
    __shared__ float sF2[16 * 256];
    __shared__ float sne[NPB * 16];
    int tid = threadIdx.x;
    int nb = blockIdx.x * NPB;
    #pragma unroll
    for (int i = 0; i < 16; i++) sF2[i * 256 + tid] = g_F2[i * 256 + tid];
    if (tid < NPB * 16) {
        int node = nb + tid / 16, k = tid & 15;
        if (node < NNODES) {
            int cnt = g_rowptr[node + 1] - g_rowptr[node] - 1;  // real in-edges
            float c = cnt < 1 ? 1.f : (float)cnt;
            sne[tid] = g_ne[(size_t)node * 16 + k] / c;
        }
    }
    __syncthreads();
    float cv = g_cv[tid];
    #pragma unroll
    for (int i = 0; i < NPB; i++) {
        int node = nb + i;
        if (node >= NNODES) break;
        float acc = cv;
        #pragma unroll
        for (int k = 0; k < 16; k++) acc += sne[i * 16 + k] * sF2[k * 256 + tid];
        g_xh[(size_t)node * 256 + tid] += acc;
    }
}

// ---------------- per-node attention coefficients ----------------
__global__ void att_kernel(const float* __restrict__ as, const float* __restrict__ ad) {
    int w = (blockIdx.x * blockDim.x + threadIdx.x) >> 5;
    int lane = threadIdx.x & 31;
    if (w >= NNODES * 4) return;
    int node = w >> 2, h = w & 3;
    const float* xr = g_xh + (size_t)node * 256 + h * 64;
    float s1 = xr[lane] * as[h * 64 + lane] + xr[lane + 32] * as[h * 64 + lane + 32];
    float s2 = xr[lane] * ad[h * 64 + lane] + xr[lane + 32] * ad[h * 64 + lane + 32];
    #pragma unroll
    for (int o = 16; o; o >>= 1) {
        s1 += __shfl_down_sync(0xffffffffu, s1, o);
        s2 += __shfl_down_sync(0xffffffffu, s2, o);
    }
    if (lane == 0) {
        g_asrc[w] = s1;
        g_adst[w] = s2;
    }
}

// ---------------- fused GAT v2: warp softmax + smem alpha + 4-wide gather ----------------
#define GNB 8      // nodes per block (50000 % 8 == 0 -> 6250 blocks exactly)
#define GCAP 96    // cached edges per node (deg ~ Poisson(16); fallback covers overflow)
__global__ __launch_bounds__(256) void gat_fused(const float* __restrict__ bias,
                                                 float* __restrict__ out) {
    __shared__ float salpha[GNB][GCAP * 4];   // [edge][head]
    __shared__ int   ssrc  [GNB][GCAP];
    __shared__ float sM[GNB][4], sDinv[GNB][4], sAdst[GNB][4];
    __shared__ int   sbeg[GNB], sdeg[GNB];

    int tid = threadIdx.x, wid = tid >> 5, lane = tid & 31;
    int node0 = blockIdx.x * GNB;

    // ---- phase 1: warp `wid` does softmax stats + alpha for node node0+wid ----
    {
        int node = node0 + wid;
        int beg = g_rowptr[node], end = g_rowptr[node + 1];
        int deg = end - beg;
        if (lane == 0) { sbeg[wid] = beg; sdeg[wid] = deg; }
        int h = lane & 3, slot = lane >> 2;            // 8 slots x 4 heads
        float adst = g_adst[node * 4 + h];
        if (lane < 4) sAdst[wid][lane] = g_adst[node * 4 + lane];
        float m = -INFINITY, dsum = 0.f;
        for (int i = slot; i < deg; i += 8) {
            int s = g_einc[beg + i];
            float l = lrelu(g_asrc[s * 4 + h] + adst);
            if (l > m) { dsum = dsum * __expf(m - l) + 1.f; m = l; }
            else       { dsum += __expf(l - m); }
        }
        // reduce over slots (xor 16,8,4) keeping head lanes aligned
        #pragma unroll
        for (int off = 16; off >= 4; off >>= 1) {
            float mo = __shfl_xor_sync(0xffffffffu, m, off);
            float d2 = __shfl_xor_sync(0xffffffffu, dsum, off);
            float M = fmaxf(m, mo);
            if (M == -INFINITY) { dsum = 0.f; }
            else dsum = dsum * __expf(m - M) + d2 * __expf(mo - M);
            m = M;
        }
        // every lane now holds its head's total (deg>=1 -> dsum>0)
        float Dinv = 1.f / dsum;
        if (lane < 4) { sM[wid][lane] = m; sDinv[wid][lane] = Dinv; }
        int cap = deg < GCAP ? deg : GCAP;
        for (int i = slot; i < cap; i += 8) {
            int s = g_einc[beg + i];
            if (h == 0) ssrc[wid][i] = s;
            float l = lrelu(g_asrc[s * 4 + h] + adst);
            salpha[wid][i * 4 + h] = __expf(l - m) * Dinv;
        }
    }
    __syncthreads();

    // ---- phase 2: 256 threads aggregate features for all GNB nodes ----
    int h2 = tid >> 6;
    float bsv = bias[tid];
    for (int n = 0; n < GNB; n++) {
        int node = node0 + n;
        int deg = sdeg[n];
        int cap = deg < GCAP ? deg : GCAP;
        float acc0 = 0.f, acc1 = 0.f;
        int e = 0;
        for (; e + 4 <= cap; e += 4) {
            int s0 = ssrc[n][e + 0], s1 = ssrc[n][e + 1];
            int s2 = ssrc[n][e + 2], s3 = ssrc[n][e + 3];
            float a0 = salpha[n][(e + 0) * 4 + h2];
            float a1 = salpha[n][(e + 1) * 4 + h2];
            float a2 = salpha[n][(e + 2) * 4 + h2];
            float a3 = salpha[n][(e + 3) * 4 + h2];
            float x0 = g_xh[(size_t)s0 * 256 + tid];
            float x1 = g_xh[(size_t)s1 * 256 + tid];
            float x2 = g_xh[(size_t)s2 * 256 + tid];
            float x3 = g_xh[(size_t)s3 * 256 + tid];
            acc0 += a0 * x0; acc1 += a1 * x1;
            acc0 += a2 * x2; acc1 += a3 * x3;
        }
        for (; e < cap; e++) {
            int s0 = ssrc[n][e];
            acc0 += salpha[n][e * 4 + h2] * g_xh[(size_t)s0 * 256 + tid];
        }
        if (deg > GCAP) {   // rare fallback: recompute alpha inline
            int beg = sbeg[n];
            float M = sM[n][h2], Dinv = sDinv[n][h2], adst = sAdst[n][h2];
            for (e = GCAP; e < deg; e++) {
                int s0 = g_einc[beg + e];
                float l = lrelu(g_asrc[s0 * 4 + h2] + adst);
                acc0 += __expf(l - M) * Dinv * g_xh[(size_t)s0 * 256 + tid];
            }
        }
        float v = acc0 + acc1 + bsv;
        out[(size_t)node * 256 + tid] = v > 0.f ? v : expm1f(v);
    }
}

// ---------------- host launch ----------------
extern "C" void kernel_launch(void* const* d_in, const int* in_sizes, int n_in,
                              void* d_out, int out_size) {
    const float* node_feats = (const float*)d_in[0];
    const float* edge_attr  = (const float*)d_in[1];
    const float* Wnp = (const float*)d_in[2];
    const float* bnp = (const float*)d_in[3];
    const float* Wep = (const float*)d_in[4];
    const float* bep = (const float*)d_in[5];
    const float* Wg1 = (const float*)d_in[6];
    const float* as1 = (const float*)d_in[7];
    const float* ad1 = (const float*)d_in[8];
    const float* bg1 = (const float*)d_in[9];
    const float* Wg2 = (const float*)d_in[10];
    const float* as2 = (const float*)d_in[11];
    const float* ad2 = (const float*)d_in[12];
    const float* bg2 = (const float*)d_in[13];
    const float* Wo  = (const float*)d_in[14];
    const float* bo  = (const float*)d_in[15];
    const int*   ei  = (const int*)d_in[16];
    float* out = (float*)d_out;

    float *pxh, *px2, *pne, *pF1, *pF2;
    int* pdeg;
    cudaGetSymbolAddress((void**)&pxh,  g_xh);
    cudaGetSymbolAddress((void**)&px2,  g_x2);
    cudaGetSymbolAddress((void**)&pne,  g_ne);
    cudaGetSymbolAddress((void**)&pF1,  g_F1);
    cudaGetSymbolAddress((void**)&pF2,  g_F2);
    cudaGetSymbolAddress((void**)&pdeg, g_deg);

    dim3 gg(2, (NNODES + BM - 1) / BM);

    // 1-3. weight fusion precompute
    fuse_w_kernel<<<128, 256>>>(Wnp, Wg1, pF1);
    fuse_w_kernel<<<16, 256>>>(Wep, Wg1 + 256 * 256, pF2);
    fuse_b_kernel<<<1, 256>>>(bnp, bep, Wg1);

    // 4. main fused GEMM: xh = node_feats @ F1   (PROFILED SLOT)
    sgemm_bias<<<gg, 256>>>(node_feats, pF1, nullptr, pxh, NNODES, 256, 128, 128, 256, 0);

    // 5-6. edge_attr scatter-sum (+ deg zero fused)
    zero2_kernel<<<((size_t)NNODES * 16 + 255) / 256, 256>>>(pne, (size_t)NNODES * 16,
                                                             pdeg, NNODES);
    edge_mean_kernel<<<(NEDGES * 16 + 255) / 256, 256>>>(edge_attr, ei);

    // 7-9. CSR build
    hist_kernel<<<(NAUG + 255) / 256, 256>>>(ei);
    scan_kernel<<<1, SCAN_T>>>();
    scatter_kernel<<<(NAUG + 255) / 256, 256>>>(ei);

    // 10. xh += nefmean @ F2 + cvec
    rank16_kernel<<<(NNODES + NPB - 1) / NPB, 256>>>();

    // 11-12. GAT layer 1 sparse part -> g_x2
    att_kernel<<<(NNODES * 4 * 32 + 255) / 256, 256>>>(as1, ad1);
    gat_fused<<<NNODES / GNB, 256>>>(bg1, px2);

    // 13-15. GAT layer 2
    sgemm_bias<<<gg, 256>>>(px2, Wg2, nullptr, pxh, NNODES, 256, 256, 256, 256, 0);
    att_kernel<<<(NNODES * 4 * 32 + 255) / 256, 256>>>(as2, ad2);
    gat_fused<<<NNODES / GNB, 256>>>(bg2, px2);

    // 16. output projection -> d_out
    sgemm_bias<<<gg, 256>>>(px2, Wo, bo, out, NNODES, 256, 256, 256, 256, 0);
}